// round 11
// baseline (speedup 1.0000x reference)
#include <cuda_runtime.h>
#include <math_constants.h>

#define IW 224
#define IH 224
#define CCH 32
#define RB 32          // output rows per block
#define TROWS 36       // RB + 4 halo
#define TSTRIDE 232    // 228 cols (224 + 4 halo) padded

// out[b,c,y,x] = max_{i,j} x[b,c,y+i-2,x+j-2] + kernel[c,0,4-i,4-j], oob -> -inf
// tile[r][c]: global row y0-2+r, global col c-2. Cols 0,1,226,227 always -inf.
__global__ void __launch_bounds__(224, 4)
tropical_conv2d_kernel(const float* __restrict__ x,
                       const float* __restrict__ kw,
                       float* __restrict__ out) {
    __shared__ float tile[TROWS][TSTRIDE];
    const float NEG = -CUDART_INF_F;

    int bx   = blockIdx.x;
    int img  = bx / 7;              // b*C + c, 0..255  (magic-mul)
    int band = bx - img * 7;        // 0..6, 7 bands x 32 rows = 224
    int tid  = threadIdx.x;
    int u    = tid % 56;            // col-quad: owns cols 4u..4u+3
    int g    = tid / 56;            // row-group 0..3
    int y0   = band * RB;

    const float* xi = x + (size_t)img * (IH * IW);
    float* oi = out + (size_t)img * (IH * IW);
    const float* kc = kw + (img & (CCH - 1)) * 25;

    // wt[i*5+j] = kernel[c,0,4-i,4-j] = kc[24 - (5i+j)]
    float wt[25];
#pragma unroll
    for (int t = 0; t < 25; ++t) wt[t] = __ldg(kc + (24 - t));

    // ---- x-halo cols (always outside image): 36 rows x 4 cols -> -inf ----
    if (tid < 144) {
        int r = tid >> 2;
        int c = tid & 3;
        c = (c < 2) ? c : (c + 224);   // cols 0,1,226,227
        tile[r][c] = NEG;
    }

    // ---- stage bulk: 36 rows x 56 quads; thread (g,u) does rows g,g+4,...,g+32 ----
#pragma unroll
    for (int k = 0; k < 9; ++k) {
        int r = g + 4 * k;
        int gr = y0 - 2 + r;
        float4 v;
        if ((unsigned)gr < (unsigned)IH) {
            v = *(const float4*)(xi + gr * IW + 4 * u);
        } else {
            v.x = NEG; v.y = NEG; v.z = NEG; v.w = NEG;
        }
        // tile col 4u+2 is 8-byte aligned -> two 64-bit stores
        float2* d = (float2*)&tile[r][4 * u + 2];
        d[0] = make_float2(v.x, v.y);
        d[1] = make_float2(v.z, v.w);
    }
    __syncthreads();

    // ---- compute: thread (g,u) owns output rows y0+8g .. y0+8g+7, cols 4u..4u+3
    //      processed as 4 pairs; each pair shares a 6-row window (12 LDS.128). ----
    int x0 = 4 * u;
    int rbase = 8 * g;
    float* op = oi + (size_t)(y0 + rbase) * IW + x0;

#pragma unroll
    for (int sp = 0; sp < 4; ++sp) {
        int s = 2 * sp;
        float a0 = NEG, a1 = NEG, a2 = NEG, a3 = NEG;   // output row rbase+s
        float b0 = NEG, b1 = NEG, b2 = NEG, b3 = NEG;   // output row rbase+s+1
#pragma unroll
        for (int r = 0; r < 6; ++r) {
            const float* trow = &tile[rbase + s + r][x0];
            float4 L = *(const float4*)(trow);      // global cols x0-2..x0+1
            float4 H = *(const float4*)(trow + 4);  // global cols x0+2..x0+5
            float W[8] = {L.x, L.y, L.z, L.w, H.x, H.y, H.z, H.w};
            if (r < 5) {          // weight row i = r for output row s
#pragma unroll
                for (int j = 0; j < 5; ++j) {
                    float wv = wt[r * 5 + j];
                    a0 = fmaxf(a0, W[j]     + wv);
                    a1 = fmaxf(a1, W[j + 1] + wv);
                    a2 = fmaxf(a2, W[j + 2] + wv);
                    a3 = fmaxf(a3, W[j + 3] + wv);
                }
            }
            if (r >= 1) {         // weight row i = r-1 for output row s+1
#pragma unroll
                for (int j = 0; j < 5; ++j) {
                    float wv = wt[(r - 1) * 5 + j];
                    b0 = fmaxf(b0, W[j]     + wv);
                    b1 = fmaxf(b1, W[j + 1] + wv);
                    b2 = fmaxf(b2, W[j + 2] + wv);
                    b3 = fmaxf(b3, W[j + 3] + wv);
                }
            }
        }
        *(float4*)op = make_float4(a0, a1, a2, a3);
        op += IW;
        *(float4*)op = make_float4(b0, b1, b2, b3);
        op += IW;
    }
}

extern "C" void kernel_launch(void* const* d_in, const int* in_sizes, int n_in,
                              void* d_out, int out_size) {
    const float* x = (const float*)d_in[0];   // (8,32,224,224) fp32
    const float* k = (const float*)d_in[1];   // (32,1,5,5) fp32
    float* out = (float*)d_out;               // (8,32,224,224) fp32
    // 256 images x 7 y-bands = 1792 blocks; 224 thr = 4 row-groups x 56 col-quads
    tropical_conv2d_kernel<<<1792, 224>>>(x, k, out);
}

// round 12
// speedup vs baseline: 1.0088x; 1.0088x over previous
#include <cuda_runtime.h>
#include <math_constants.h>

#define IW 224
#define IH 224
#define CCH 32
#define RB 32          // output rows per block
#define TROWS 36       // RB + 4 halo
#define TSTRIDE 232    // 228 cols (224 + 4 halo) padded

// out[b,c,y,x] = max_{i,j} x[b,c,y+i-2,x+j-2] + kernel[c,0,4-i,4-j], oob -> -inf
// tile[r][c]: global row y0-2+r, global col c-2. Cols 0,1,226,227 always -inf.
__global__ void __launch_bounds__(224, 5)
tropical_conv2d_kernel(const float* __restrict__ x,
                       const float* __restrict__ kw,
                       float* __restrict__ out) {
    __shared__ float tile[TROWS][TSTRIDE];
    __shared__ float swt[25];          // flipped weights, block-shared
    const float NEG = -CUDART_INF_F;

    int bx   = blockIdx.x;
    int img  = bx / 7;              // b*C + c, 0..255  (magic-mul)
    int band = bx - img * 7;        // 0..6, 7 bands x 32 rows = 224
    int tid  = threadIdx.x;
    int u    = tid % 56;            // col-quad: owns cols 4u..4u+3
    int g    = tid / 56;            // row-group 0..3
    int y0   = band * RB;

    const float* xi = x + (size_t)img * (IH * IW);
    float* oi = out + (size_t)img * (IH * IW);
    const float* kc = kw + (img & (CCH - 1)) * 25;

    // swt[i*5+j] = kernel[c,0,4-i,4-j] = kc[24 - (5i+j)]
    if (tid < 25) swt[tid] = __ldg(kc + (24 - tid));

    // ---- x-halo cols (always outside image): 36 rows x 4 cols -> -inf ----
    if (tid < 144) {
        int r = tid >> 2;
        int c = tid & 3;
        c = (c < 2) ? c : (c + 224);   // cols 0,1,226,227
        tile[r][c] = NEG;
    }

    // ---- stage bulk: 36 rows x 56 quads; thread (g,u) does rows g,g+4,...,g+32 ----
#pragma unroll
    for (int k = 0; k < 9; ++k) {
        int r = g + 4 * k;
        int gr = y0 - 2 + r;
        float4 v;
        if ((unsigned)gr < (unsigned)IH) {
            v = *(const float4*)(xi + gr * IW + 4 * u);
        } else {
            v.x = NEG; v.y = NEG; v.z = NEG; v.w = NEG;
        }
        // tile col 4u+2 is 8-byte aligned -> two 64-bit stores
        float2* d = (float2*)&tile[r][4 * u + 2];
        d[0] = make_float2(v.x, v.y);
        d[1] = make_float2(v.z, v.w);
    }
    __syncthreads();

    // ---- compute: thread (g,u) owns output rows y0+8g .. y0+8g+7, cols 4u..4u+3
    //      processed as 4 pairs; pair shares a 6-row window (12 LDS.128).
    //      Weight rows loaded JIT from smem: wr = row r (for a), wp = row r-1 (for b). ----
    int x0 = 4 * u;
    int rbase = 8 * g;
    float* op = oi + (size_t)(y0 + rbase) * IW + x0;

#pragma unroll
    for (int sp = 0; sp < 4; ++sp) {
        float a0 = NEG, a1 = NEG, a2 = NEG, a3 = NEG;   // output row rbase+2sp
        float b0 = NEG, b1 = NEG, b2 = NEG, b3 = NEG;   // output row rbase+2sp+1
        float wr[5], wp[5];
#pragma unroll
        for (int r = 0; r < 6; ++r) {
            const float* trow = &tile[rbase + 2 * sp + r][x0];
            float4 L = *(const float4*)(trow);      // global cols x0-2..x0+1
            float4 H = *(const float4*)(trow + 4);  // global cols x0+2..x0+5
            float W[8] = {L.x, L.y, L.z, L.w, H.x, H.y, H.z, H.w};
            if (r >= 1) {       // b-row uses previous a-row weights (SSA rename)
#pragma unroll
                for (int j = 0; j < 5; ++j) wp[j] = wr[j];
            }
            if (r < 5) {        // load weight row r (broadcast LDS, conflict-free)
#pragma unroll
                for (int j = 0; j < 5; ++j) wr[j] = swt[r * 5 + j];
#pragma unroll
                for (int j = 0; j < 5; ++j) {
                    float wv = wr[j];
                    a0 = fmaxf(a0, W[j]     + wv);
                    a1 = fmaxf(a1, W[j + 1] + wv);
                    a2 = fmaxf(a2, W[j + 2] + wv);
                    a3 = fmaxf(a3, W[j + 3] + wv);
                }
            }
            if (r >= 1) {
#pragma unroll
                for (int j = 0; j < 5; ++j) {
                    float wv = wp[j];
                    b0 = fmaxf(b0, W[j]     + wv);
                    b1 = fmaxf(b1, W[j + 1] + wv);
                    b2 = fmaxf(b2, W[j + 2] + wv);
                    b3 = fmaxf(b3, W[j + 3] + wv);
                }
            }
        }
        *(float4*)op = make_float4(a0, a1, a2, a3);
        op += IW;
        *(float4*)op = make_float4(b0, b1, b2, b3);
        op += IW;
    }
}

extern "C" void kernel_launch(void* const* d_in, const int* in_sizes, int n_in,
                              void* d_out, int out_size) {
    const float* x = (const float*)d_in[0];   // (8,32,224,224) fp32
    const float* k = (const float*)d_in[1];   // (32,1,5,5) fp32
    float* out = (float*)d_out;               // (8,32,224,224) fp32
    // 256 images x 7 y-bands = 1792 blocks; 224 thr = 4 row-groups x 56 col-quads
    tropical_conv2d_kernel<<<1792, 224>>>(x, k, out);
}